// round 15
// baseline (speedup 1.0000x reference)
#include <cuda_runtime.h>
#include <cuda_bf16.h>
#include <cstdint>
#include <cstddef>
#include <cstring>

// ----------------------------------------------------------------------------
// B=32, S=512, E=512, U=1024, G=4096.  out = (h, h, c) : 3*32*1024 f32
// Persistent fused kernel: z_t = [h_t ; x_t] @ [U ; W] + bias.
// Round-15 changes: (1) hierarchical grid barrier (cluster mbarrier collapse,
// 32 leader atomics, DSMEM multicast release); (2) x-chunk mma runs first to
// hide the B-h L2 round-trip (h loads in regs during x work).
// Base: round-14 winner (3496 us).
// ----------------------------------------------------------------------------
#define NCTA 128

__device__ __nv_bfloat16  g_hh[2][32768];              // h hi, [b][u]
__device__ __nv_bfloat16  g_hl[2][32768];              // h lo
__device__ uint4          g_pkA_hi[786432];            // [U;W] packed A-frags hi
__device__ uint4          g_pkA_lo[786432];            // [U;W] packed A-frags lo
__device__ int            g_tokens[16384];             // [b*512+t]
__device__ unsigned       g_cnt;
__device__ volatile unsigned g_gen;

// smem layout (dynamic, 166400 B): same as round 14
#define SM_XOFF  33792
#define SM_XHALF 8704
#define SM_ALO   51200
#define SM_SPART 149504
#define SM_TOTAL 166400

// ---------------- helpers ----------------
__device__ __forceinline__ int detect_is64(const int* raw, int thr, int* s_flag)
{
    if (thr == 0) *s_flag = 1;
    __syncthreads();
    if (thr < 128 && raw[2 * thr + 1] != 0) *s_flag = 0;
    __syncthreads();
    return *s_flag;
}
__device__ __forceinline__ unsigned short bf_hi(float f, float& rem) {
    __nv_bfloat16 b = __float2bfloat16(f);
    rem = f - __bfloat162float(b);
    unsigned short u; memcpy(&u, &b, 2); return u;
}
__device__ __forceinline__ unsigned short bf_of(float f) {
    __nv_bfloat16 b = __float2bfloat16(f);
    unsigned short u; memcpy(&u, &b, 2); return u;
}
__device__ __forceinline__ uint32_t smem_u32(const void* p) {
    uint32_t a;
    asm("{ .reg .u64 t; cvta.to.shared.u64 t, %1; cvt.u32.u64 %0, t; }" : "=r"(a) : "l"(p));
    return a;
}
__device__ __forceinline__ uint4 ldcg4(const uint4* p) {
    uint4 v;
    asm volatile("ld.global.cg.v4.u32 {%0,%1,%2,%3}, [%4];"
                 : "=r"(v.x), "=r"(v.y), "=r"(v.z), "=r"(v.w) : "l"(p));
    return v;
}
#define LDSM4(r0, r1, r2, r3, addr) \
    asm volatile("ldmatrix.sync.aligned.m8n8.x4.shared.b16 {%0,%1,%2,%3}, [%4];" \
                 : "=r"(r0), "=r"(r1), "=r"(r2), "=r"(r3) : "r"(addr))
#define MMA_BF16(d, ax, ay, az, aw, b0, b1) \
    asm volatile("mma.sync.aligned.m16n8k16.row.col.f32.bf16.bf16.f32 " \
                 "{%0,%1,%2,%3}, {%4,%5,%6,%7}, {%8,%9}, {%0,%1,%2,%3};" \
                 : "+f"((d)[0]), "+f"((d)[1]), "+f"((d)[2]), "+f"((d)[3]) \
                 : "r"(ax), "r"(ay), "r"(az), "r"(aw), "r"(b0), "r"(b1))

// mbarrier ops (cluster DSMEM sync)
__device__ __forceinline__ void mbar_init(uint32_t mb, uint32_t cnt) {
    asm volatile("mbarrier.init.shared.b64 [%0], %1;" :: "r"(mb), "r"(cnt) : "memory");
}
__device__ __forceinline__ void mbar_arrive_rank(uint32_t mb, uint32_t rank) {
    asm volatile("{\n\t.reg .b32 r;\n\t"
                 "mapa.shared::cluster.u32 r, %0, %1;\n\t"
                 "mbarrier.arrive.shared::cluster.b64 _, [r];\n\t}"
                 :: "r"(mb), "r"(rank) : "memory");
}
__device__ __forceinline__ void mbar_wait(uint32_t mb, uint32_t par) {
    asm volatile("{\n\t.reg .pred P1;\n\t"
                 "WL_%=:\n\t"
                 "mbarrier.try_wait.parity.acquire.cta.shared::cta.b64 P1, [%0], %1, 0x989680;\n\t"
                 "@P1 bra.uni WD_%=;\n\t"
                 "bra.uni WL_%=;\n\t"
                 "WD_%=:\n\t}" :: "r"(mb), "r"(par) : "memory");
}
__device__ __forceinline__ uint32_t mapa_rank(uint32_t addr, uint32_t rank) {
    uint32_t r;
    asm("mapa.shared::cluster.u32 %0, %1, %2;" : "=r"(r) : "r"(addr), "r"(rank));
    return r;
}
__device__ __forceinline__ float ld_dsmem_f32(uint32_t addr) {
    float v;
    asm volatile("ld.shared::cluster.f32 %0, [%1];" : "=f"(v) : "r"(addr));
    return v;
}

// ----------------------------------------------------------------------------
// pack [U;W] into per-thread mma A-fragment order (proven).
// ----------------------------------------------------------------------------
__global__ void __launch_bounds__(256) pack_UW_kernel(
    const float* __restrict__ U, const float* __restrict__ W)
{
    int idx  = blockIdx.x * 256 + threadIdx.x;
    int lane = idx & 31;
    int tmp  = idx >> 5;
    int c    = tmp % 24;
    int tmp2 = tmp / 24;
    int w    = tmp2 & 7;
    int cta  = tmp2 >> 3;
    int jb = cta >> 2, ks = cta & 3, u0 = jb << 5;
    int m0 = (w << 4) + (lane >> 2), m1 = m0 + 8;
    int j0 = ((m0 >> 5) << 10) + u0 + (m0 & 31);
    int j1 = ((m1 >> 5) << 10) + u0 + (m1 & 31);

    const float* base;
    if (c < 16) base = U + (size_t)((ks << 8) + (c << 4) + ((lane & 3) << 1)) * 4096;
    else        base = W + (size_t)((ks << 7) + ((c - 16) << 4) + ((lane & 3) << 1)) * 4096;

    float f[4][2];
    f[0][0] = base[j0];              f[0][1] = base[4096 + j0];
    f[1][0] = base[j1];              f[1][1] = base[4096 + j1];
    f[2][0] = base[8 * 4096 + j0];   f[2][1] = base[9 * 4096 + j0];
    f[3][0] = base[8 * 4096 + j1];   f[3][1] = base[9 * 4096 + j1];
    uint32_t hi[4], lo[4];
#pragma unroll
    for (int r = 0; r < 4; ++r) {
        float rm0, rm1;
        unsigned short h0 = bf_hi(f[r][0], rm0), h1 = bf_hi(f[r][1], rm1);
        hi[r] = (uint32_t)h0 | ((uint32_t)h1 << 16);
        lo[r] = (uint32_t)bf_of(rm0) | ((uint32_t)bf_of(rm1) << 16);
    }
    g_pkA_hi[idx] = make_uint4(hi[0], hi[1], hi[2], hi[3]);
    g_pkA_lo[idx] = make_uint4(lo[0], lo[1], lo[2], lo[3]);
}

// ---------------- classic grid barrier (prologue only, proven) ----------------
__device__ __forceinline__ void grid_barrier()
{
    __threadfence();
    __syncthreads();
    if (threadIdx.x == 0) {
        unsigned g = g_gen;
        if (atomicAdd(&g_cnt, 1u) == (NCTA - 1u)) {
            g_cnt = 0;
            __threadfence();
            g_gen = g + 1;
        } else {
            while (g_gen == g) { __nanosleep(32); }
        }
    }
    __syncthreads();
}

// ---------------- hierarchical grid barrier (mainloop) ----------------
// bar2: rank0's collapse mbarrier (count 4); rel: per-CTA release (count 1).
__device__ __forceinline__ void hier_barrier(uint32_t bar2, uint32_t rel,
                                             int rank, uint32_t par)
{
    __threadfence();
    __syncthreads();
    if (threadIdx.x == 0) {
        mbar_arrive_rank(bar2, 0);              // collapse into rank0
        if (rank == 0) {
            mbar_wait(bar2, par);
            unsigned g = g_gen;
            if (atomicAdd(&g_cnt, 1u) == 31u) { // 32 cluster leaders
                g_cnt = 0;
                __threadfence();
                g_gen = g + 1;
            } else {
                while (g_gen == g) { }
            }
#pragma unroll
            for (int r = 0; r < 4; ++r) mbar_arrive_rank(rel, r);
        }
        mbar_wait(rel, par);
    }
    __syncthreads();
}

// ----------------------------------------------------------------------------
// Fused LSTM scan: 32 clusters x 4 CTAs, 256 thr.  cta = jb*4 + ks, rank = ks.
// ----------------------------------------------------------------------------
__global__ void __launch_bounds__(256, 1) __cluster_dims__(4, 1, 1)
lstm_kernel(
    const int*   __restrict__ raw,
    const float* __restrict__ emb,
    const float* __restrict__ bias,
    float*       __restrict__ out)
{
    extern __shared__ __align__(16) char sm[];
    __shared__ __align__(8) unsigned long long s_mbar;   // phase exchange (count 4)
    __shared__ __align__(8) unsigned long long s_bar2;   // barrier collapse (count 4)
    __shared__ __align__(8) unsigned long long s_rel;    // barrier release (count 1)
    __shared__ int s_is64;

    const int thr  = threadIdx.x;
    const int lane = thr & 31;
    const int w    = thr >> 5;
    const int cta  = blockIdx.x;
    const int ks   = cta & 3;                 // == cluster rank
    const int u0   = (cta >> 2) << 5;
    const int is64 = detect_is64(raw, thr, &s_is64);

    if (thr < 128) {
        int i = cta * 128 + thr;
        g_tokens[i] = is64 ? raw[2 * i] : raw[i];
    }
    {
        int zt = cta * 256 + thr;
        unsigned short z = 0;
        *(unsigned short*)&g_hh[0][zt] = z;
        *(unsigned short*)&g_hl[0][zt] = z;
    }

    const uint32_t mbAddr  = smem_u32(&s_mbar);
    const uint32_t barAddr = smem_u32(&s_bar2);
    const uint32_t relAddr = smem_u32(&s_rel);
    if (thr == 0) {
        mbar_init(mbAddr, 4);
        mbar_init(barAddr, 4);
        mbar_init(relAddr, 1);
    }

    // mma geometry (proven)
    const uint32_t sbB = smem_u32(sm);
    const uint32_t sbX = sbB + SM_XOFF;
    const int tile = lane >> 3, rsel = lane & 7;
    const int nrowoff = ((tile >> 1) & 1) * 8 + rsel;
    const int koff    = (tile & 1) * 16;
    const int abase   = (cta * 8 + w) * 768 + lane;
    const int m_r  = (w << 4) + (lane >> 2);
    const int m_r8 = m_r + 8;

    // A-lo fragments -> private smem slots (proven win)
    char* aloPtr = sm + SM_ALO + (size_t)(w * 768 + lane) * 16;
    {
        const uint4* src = g_pkA_lo + abase;
#pragma unroll
        for (int c = 0; c < 24; ++c)
            *(uint4*)(aloPtr + c * 512) = __ldg(src + c * 32);
    }
    grid_barrier();    // tokens, h0, mbar inits visible grid/cluster-wide

    // phase-2 ownership (cluster-local)
    const int bl  = thr >> 5;
    const int uu  = thr & 31;
    const int b2  = ks * 8 + bl;
    const int u2  = u0 + uu;
    float hreg = 0.f, creg = 0.f;
    float biasr[4];
#pragma unroll
    for (int g = 0; g < 4; ++g) biasr[g] = bias[g * 1024 + u2];
    int tokv = g_tokens[b2 * 512];

    const uint32_t sbPart = sbB + SM_SPART;
    uint32_t rAddr[4];
#pragma unroll
    for (int r = 0; r < 4; ++r) rAddr[r] = mapa_rank(sbPart, r);
    float* zb = (float*)(sm + SM_SPART);

    // B-h staging maps (row/q fixed per thread)
    int hRowOff[8], hDst[8];
#pragma unroll
    for (int ii = 0; ii < 8; ++ii) {
        int idx  = ii * 256 + thr;
        int hsel = idx >> 10;
        int rq   = idx & 1023;
        int row  = rq >> 5, q = rq & 31;
        hRowOff[ii] = (hsel << 16) | (row * 1024 + q * 8);  // hsel + elem offset
        hDst[ii]    = hsel * 16896 + row * 528 + q * 16;
    }
    // x staging mapping
    const int xrow = thr >> 3;
    const int xq   = thr & 7;

    for (int t = 0; t < 512; ++t) {
        // ---- (1) issue B-h loads into regs (L2 RT hidden behind x work) ----
        const __nv_bfloat16* hcur0 = g_hh[t & 1] + ks * 256;
        const __nv_bfloat16* hcur1 = g_hl[t & 1] + ks * 256;
        uint4 hv[8];
#pragma unroll
        for (int ii = 0; ii < 8; ++ii) {
            const __nv_bfloat16* src =
                ((hRowOff[ii] >> 16) ? hcur1 : hcur0) + (hRowOff[ii] & 0xFFFF);
            hv[ii] = ldcg4((const uint4*)src);
        }
        // ---- (2) stage B-x: emb gather fp32 -> hi/lo bf16 ----
        {
            int tokx = g_tokens[xrow * 512 + t];
            const float* xs = emb + (size_t)tokx * 512 + ks * 128 + xq * 16;
            uint32_t hiw[8], low[8];
#pragma unroll
            for (int p = 0; p < 4; ++p) {
                float4 v = __ldg((const float4*)(xs + p * 4));
                float r0, r1, r2, r3;
                unsigned short h0 = bf_hi(v.x, r0), h1 = bf_hi(v.y, r1);
                unsigned short h2 = bf_hi(v.z, r2), h3 = bf_hi(v.w, r3);
                hiw[p * 2]     = (uint32_t)h0 | ((uint32_t)h1 << 16);
                hiw[p * 2 + 1] = (uint32_t)h2 | ((uint32_t)h3 << 16);
                low[p * 2]     = (uint32_t)bf_of(r0) | ((uint32_t)bf_of(r1) << 16);
                low[p * 2 + 1] = (uint32_t)bf_of(r2) | ((uint32_t)bf_of(r3) << 16);
            }
            char* xd = sm + SM_XOFF + xrow * 272 + xq * 32;
            *(uint4*)xd        = make_uint4(hiw[0], hiw[1], hiw[2], hiw[3]);
            *(uint4*)(xd + 16) = make_uint4(hiw[4], hiw[5], hiw[6], hiw[7]);
            *(uint4*)(xd + SM_XHALF)      = make_uint4(low[0], low[1], low[2], low[3]);
            *(uint4*)(xd + SM_XHALF + 16) = make_uint4(low[4], low[5], low[6], low[7]);
        }
        __syncthreads();

        float d[4][4];
#pragma unroll
        for (int nf = 0; nf < 4; ++nf)
#pragma unroll
            for (int i = 0; i < 4; ++i) d[nf][i] = 0.f;

        // ---- (3) x-chunk mma (16..23) while B-h loads are in flight ----
        {
            uint4 ahP0 = __ldg(&g_pkA_hi[abase + 16 * 32]);
            uint4 ahP1 = __ldg(&g_pkA_hi[abase + 17 * 32]);
#pragma unroll
            for (int cl = 0; cl < 8; ++cl) {
                const int c = 16 + cl;
                uint4 ah = ahP0;
                ahP0 = ahP1;
                if (cl + 2 < 8) ahP1 = __ldg(&g_pkA_hi[abase + (c + 2) * 32]);
                uint4 al = *(const uint4*)(aloPtr + c * 512);
                uint32_t a0 = sbX + nrowoff * 272 + cl * 32 + koff;
                uint32_t a1 = a0 + 16 * 272;
                uint32_t bh[8], bl8[8];
                LDSM4(bh[0], bh[1], bh[2], bh[3], a0);
                LDSM4(bh[4], bh[5], bh[6], bh[7], a1);
                LDSM4(bl8[0], bl8[1], bl8[2], bl8[3], a0 + SM_XHALF);
                LDSM4(bl8[4], bl8[5], bl8[6], bl8[7], a1 + SM_XHALF);
#pragma unroll
                for (int nf = 0; nf < 4; ++nf) {
                    MMA_BF16(d[nf], ah.x, ah.y, ah.z, ah.w, bh[nf * 2], bh[nf * 2 + 1]);
                    MMA_BF16(d[nf], ah.x, ah.y, ah.z, ah.w, bl8[nf * 2], bl8[nf * 2 + 1]);
                    MMA_BF16(d[nf], al.x, al.y, al.z, al.w, bh[nf * 2], bh[nf * 2 + 1]);
                }
            }
        }
        // ---- (4) commit B-h regs to smem, sync ----
#pragma unroll
        for (int ii = 0; ii < 8; ++ii)
            *(uint4*)(sm + hDst[ii]) = hv[ii];
        __syncthreads();

        // ---- (5) h-chunk mma (0..15) ----
        {
            uint4 ahP0 = ldcg4(&g_pkA_hi[abase]);
            uint4 ahP1 = ldcg4(&g_pkA_hi[abase + 32]);
#pragma unroll
            for (int c = 0; c < 16; ++c) {
                uint4 ah = ahP0;
                ahP0 = ahP1;
                if (c + 2 < 16) {
                    if (c + 2 < 8) ahP1 = ldcg4(&g_pkA_hi[abase + (c + 2) * 32]);
                    else           ahP1 = __ldg(&g_pkA_hi[abase + (c + 2) * 32]);
                }
                uint4 al = *(const uint4*)(aloPtr + c * 512);
                uint32_t a0 = sbB + nrowoff * 528 + c * 32 + koff;
                uint32_t a1 = a0 + 16 * 528;
                uint32_t bh[8], bl8[8];
                LDSM4(bh[0], bh[1], bh[2], bh[3], a0);
                LDSM4(bh[4], bh[5], bh[6], bh[7], a1);
                LDSM4(bl8[0], bl8[1], bl8[2], bl8[3], a0 + 16896);
                LDSM4(bl8[4], bl8[5], bl8[6], bl8[7], a1 + 16896);
#pragma unroll
                for (int nf = 0; nf < 4; ++nf) {
                    MMA_BF16(d[nf], ah.x, ah.y, ah.z, ah.w, bh[nf * 2], bh[nf * 2 + 1]);
                    MMA_BF16(d[nf], ah.x, ah.y, ah.z, ah.w, bl8[nf * 2], bl8[nf * 2 + 1]);
                    MMA_BF16(d[nf], al.x, al.y, al.z, al.w, bh[nf * 2], bh[nf * 2 + 1]);
                }
            }
        }

        // ---- partial z tile -> LOCAL smem ----
#pragma unroll
        for (int nf = 0; nf < 4; ++nf) {
            int bcol = nf * 8 + ((lane & 3) << 1);
            zb[bcol * 132 + m_r]        = d[nf][0];
            zb[(bcol + 1) * 132 + m_r]  = d[nf][1];
            zb[bcol * 132 + m_r8]       = d[nf][2];
            zb[(bcol + 1) * 132 + m_r8] = d[nf][3];
        }
        __syncthreads();                  // drains STS
        if (thr < 4) mbar_arrive_rank(mbAddr, (uint32_t)thr);
        mbar_wait(mbAddr, t & 1);

        // ---- phase 2: pull 4 sibling partials via DSMEM, gates ----
        {
            float z[4];
#pragma unroll
            for (int g = 0; g < 4; ++g) {
                uint32_t off = (uint32_t)(b2 * 132 + g * 32 + uu) * 4;
                float s = biasr[g];
#pragma unroll
                for (int r = 0; r < 4; ++r)
                    s += ld_dsmem_f32(rAddr[r] + off);
                z[g] = s;
            }
            float gi = tanhf(z[0]);
            float gf = tanhf(z[1]);
            float gg = tanhf(z[2]);
            float go = tanhf(z[3]);
            float cn = fmaf(gf, creg, gi * gg);
            float hn = go * tanhf(cn);
            if (tokv != 0) { creg = cn; hreg = hn; }
            float rem;
            unsigned short hb = bf_hi(hreg, rem);
            int ho = b2 * 1024 + u2;
            *(unsigned short*)&g_hh[(t + 1) & 1][ho] = hb;
            *(unsigned short*)&g_hl[(t + 1) & 1][ho] = bf_of(rem);

            if (t + 1 < 512) tokv = g_tokens[b2 * 512 + t + 1];
        }
        hier_barrier(barAddr, relAddr, ks, (uint32_t)(t & 1));
    }

    {
        int o = b2 * 1024 + u2;
        out[o]         = hreg;
        out[32768 + o] = hreg;
        out[65536 + o] = creg;
    }
}

// ---------------- launch ----------------
extern "C" void kernel_launch(void* const* d_in, const int* in_sizes, int n_in,
                              void* d_out, int out_size)
{
    const int*   tokens_raw = (const int*)  d_in[0];
    const float* emb        = (const float*)d_in[1];
    const float* W          = (const float*)d_in[2];
    const float* U          = (const float*)d_in[3];
    const float* bias       = (const float*)d_in[4];
    float*       out        = (float*)d_out;
    (void)in_sizes; (void)n_in; (void)out_size;

    cudaFuncSetAttribute(lstm_kernel,
                         cudaFuncAttributeMaxDynamicSharedMemorySize, SM_TOTAL);

    pack_UW_kernel<<<3072, 256>>>(U, W);
    lstm_kernel<<<NCTA, 256, SM_TOTAL>>>(tokens_raw, emb, bias, out);
}

// round 16
// speedup vs baseline: 1.0429x; 1.0429x over previous
#include <cuda_runtime.h>
#include <cuda_bf16.h>
#include <cstdint>
#include <cstddef>
#include <cstring>

// ----------------------------------------------------------------------------
// B=32, S=512, E=512, U=1024, G=4096.  out = (h, h, c) : 3*32*1024 f32
// Persistent fused kernel: z_t = [h_t ; x_t] @ [U ; W] + bias.
// Round-16 change (ONLY): x-chunk mma runs first while B-h loads (issued into
// registers at step start) complete -> hides the h L2 round-trip.
// Base: round-14 winner (3496 us). Barrier & phase2 byte-identical to R14.
// ----------------------------------------------------------------------------
#define NCTA 128

__device__ __nv_bfloat16  g_hh[2][32768];              // h hi, [b][u]
__device__ __nv_bfloat16  g_hl[2][32768];              // h lo
__device__ uint4          g_pkA_hi[786432];            // [U;W] packed A-frags hi
__device__ uint4          g_pkA_lo[786432];            // [U;W] packed A-frags lo
__device__ int            g_tokens[16384];             // [b*512+t]
__device__ unsigned       g_cnt;
__device__ volatile unsigned g_gen;

// smem layout (dynamic, 166400 B): same as round 14
#define SM_XOFF  33792
#define SM_XHALF 8704
#define SM_ALO   51200
#define SM_SPART 149504
#define SM_TOTAL 166400

// ---------------- helpers ----------------
__device__ __forceinline__ int detect_is64(const int* raw, int thr, int* s_flag)
{
    if (thr == 0) *s_flag = 1;
    __syncthreads();
    if (thr < 128 && raw[2 * thr + 1] != 0) *s_flag = 0;
    __syncthreads();
    return *s_flag;
}
__device__ __forceinline__ unsigned short bf_hi(float f, float& rem) {
    __nv_bfloat16 b = __float2bfloat16(f);
    rem = f - __bfloat162float(b);
    unsigned short u; memcpy(&u, &b, 2); return u;
}
__device__ __forceinline__ unsigned short bf_of(float f) {
    __nv_bfloat16 b = __float2bfloat16(f);
    unsigned short u; memcpy(&u, &b, 2); return u;
}
__device__ __forceinline__ uint32_t smem_u32(const void* p) {
    uint32_t a;
    asm("{ .reg .u64 t; cvta.to.shared.u64 t, %1; cvt.u32.u64 %0, t; }" : "=r"(a) : "l"(p));
    return a;
}
__device__ __forceinline__ uint4 ldcg4(const uint4* p) {
    uint4 v;
    asm volatile("ld.global.cg.v4.u32 {%0,%1,%2,%3}, [%4];"
                 : "=r"(v.x), "=r"(v.y), "=r"(v.z), "=r"(v.w) : "l"(p));
    return v;
}
#define LDSM4(r0, r1, r2, r3, addr) \
    asm volatile("ldmatrix.sync.aligned.m8n8.x4.shared.b16 {%0,%1,%2,%3}, [%4];" \
                 : "=r"(r0), "=r"(r1), "=r"(r2), "=r"(r3) : "r"(addr))
#define MMA_BF16(d, ax, ay, az, aw, b0, b1) \
    asm volatile("mma.sync.aligned.m16n8k16.row.col.f32.bf16.bf16.f32 " \
                 "{%0,%1,%2,%3}, {%4,%5,%6,%7}, {%8,%9}, {%0,%1,%2,%3};" \
                 : "+f"((d)[0]), "+f"((d)[1]), "+f"((d)[2]), "+f"((d)[3]) \
                 : "r"(ax), "r"(ay), "r"(az), "r"(aw), "r"(b0), "r"(b1))

// mbarrier ops (cluster DSMEM sync)
__device__ __forceinline__ void mbar_init(uint32_t mb, uint32_t cnt) {
    asm volatile("mbarrier.init.shared.b64 [%0], %1;" :: "r"(mb), "r"(cnt) : "memory");
}
__device__ __forceinline__ void mbar_arrive_rank(uint32_t mb, uint32_t rank) {
    asm volatile("{\n\t.reg .b32 r;\n\t"
                 "mapa.shared::cluster.u32 r, %0, %1;\n\t"
                 "mbarrier.arrive.shared::cluster.b64 _, [r];\n\t}"
                 :: "r"(mb), "r"(rank) : "memory");
}
__device__ __forceinline__ void mbar_wait(uint32_t mb, uint32_t par) {
    asm volatile("{\n\t.reg .pred P1;\n\t"
                 "WL_%=:\n\t"
                 "mbarrier.try_wait.parity.acquire.cta.shared::cta.b64 P1, [%0], %1, 0x989680;\n\t"
                 "@P1 bra.uni WD_%=;\n\t"
                 "bra.uni WL_%=;\n\t"
                 "WD_%=:\n\t}" :: "r"(mb), "r"(par) : "memory");
}
__device__ __forceinline__ uint32_t mapa_rank(uint32_t addr, uint32_t rank) {
    uint32_t r;
    asm("mapa.shared::cluster.u32 %0, %1, %2;" : "=r"(r) : "r"(addr), "r"(rank));
    return r;
}
__device__ __forceinline__ float ld_dsmem_f32(uint32_t addr) {
    float v;
    asm volatile("ld.shared::cluster.f32 %0, [%1];" : "=f"(v) : "r"(addr));
    return v;
}

// ----------------------------------------------------------------------------
// pack [U;W] into per-thread mma A-fragment order (proven).
// ----------------------------------------------------------------------------
__global__ void __launch_bounds__(256) pack_UW_kernel(
    const float* __restrict__ U, const float* __restrict__ W)
{
    int idx  = blockIdx.x * 256 + threadIdx.x;
    int lane = idx & 31;
    int tmp  = idx >> 5;
    int c    = tmp % 24;
    int tmp2 = tmp / 24;
    int w    = tmp2 & 7;
    int cta  = tmp2 >> 3;
    int jb = cta >> 2, ks = cta & 3, u0 = jb << 5;
    int m0 = (w << 4) + (lane >> 2), m1 = m0 + 8;
    int j0 = ((m0 >> 5) << 10) + u0 + (m0 & 31);
    int j1 = ((m1 >> 5) << 10) + u0 + (m1 & 31);

    const float* base;
    if (c < 16) base = U + (size_t)((ks << 8) + (c << 4) + ((lane & 3) << 1)) * 4096;
    else        base = W + (size_t)((ks << 7) + ((c - 16) << 4) + ((lane & 3) << 1)) * 4096;

    float f[4][2];
    f[0][0] = base[j0];              f[0][1] = base[4096 + j0];
    f[1][0] = base[j1];              f[1][1] = base[4096 + j1];
    f[2][0] = base[8 * 4096 + j0];   f[2][1] = base[9 * 4096 + j0];
    f[3][0] = base[8 * 4096 + j1];   f[3][1] = base[9 * 4096 + j1];
    uint32_t hi[4], lo[4];
#pragma unroll
    for (int r = 0; r < 4; ++r) {
        float rm0, rm1;
        unsigned short h0 = bf_hi(f[r][0], rm0), h1 = bf_hi(f[r][1], rm1);
        hi[r] = (uint32_t)h0 | ((uint32_t)h1 << 16);
        lo[r] = (uint32_t)bf_of(rm0) | ((uint32_t)bf_of(rm1) << 16);
    }
    g_pkA_hi[idx] = make_uint4(hi[0], hi[1], hi[2], hi[3]);
    g_pkA_lo[idx] = make_uint4(lo[0], lo[1], lo[2], lo[3]);
}

// ---------------- grid barrier (proven) ----------------
__device__ __forceinline__ void grid_barrier()
{
    __threadfence();
    __syncthreads();
    if (threadIdx.x == 0) {
        unsigned g = g_gen;
        if (atomicAdd(&g_cnt, 1u) == (NCTA - 1u)) {
            g_cnt = 0;
            __threadfence();
            g_gen = g + 1;
        } else {
            while (g_gen == g) { __nanosleep(32); }
        }
    }
    __syncthreads();
}

// ----------------------------------------------------------------------------
// Fused LSTM scan: 32 clusters x 4 CTAs, 256 thr.  cta = jb*4 + ks, rank = ks.
// ----------------------------------------------------------------------------
__global__ void __launch_bounds__(256, 1) __cluster_dims__(4, 1, 1)
lstm_kernel(
    const int*   __restrict__ raw,
    const float* __restrict__ emb,
    const float* __restrict__ bias,
    float*       __restrict__ out)
{
    extern __shared__ __align__(16) char sm[];
    __shared__ __align__(8) unsigned long long s_mbar;
    __shared__ int s_is64;

    const int thr  = threadIdx.x;
    const int lane = thr & 31;
    const int w    = thr >> 5;
    const int cta  = blockIdx.x;
    const int ks   = cta & 3;                 // == cluster rank
    const int u0   = (cta >> 2) << 5;
    const int is64 = detect_is64(raw, thr, &s_is64);

    if (thr < 128) {
        int i = cta * 128 + thr;
        g_tokens[i] = is64 ? raw[2 * i] : raw[i];
    }
    {
        int zt = cta * 256 + thr;
        unsigned short z = 0;
        *(unsigned short*)&g_hh[0][zt] = z;
        *(unsigned short*)&g_hl[0][zt] = z;
    }

    const uint32_t mbAddr = smem_u32(&s_mbar);
    if (thr == 0) mbar_init(mbAddr, 4);

    // mma geometry (proven)
    const uint32_t sbB = smem_u32(sm);
    const uint32_t sbX = sbB + SM_XOFF;
    const int tile = lane >> 3, rsel = lane & 7;
    const int nrowoff = ((tile >> 1) & 1) * 8 + rsel;
    const int koff    = (tile & 1) * 16;
    const int abase   = (cta * 8 + w) * 768 + lane;
    const int m_r  = (w << 4) + (lane >> 2);
    const int m_r8 = m_r + 8;

    // A-lo fragments -> private smem slots (proven win)
    char* aloPtr = sm + SM_ALO + (size_t)(w * 768 + lane) * 16;
    {
        const uint4* src = g_pkA_lo + abase;
#pragma unroll
        for (int c = 0; c < 24; ++c)
            *(uint4*)(aloPtr + c * 512) = __ldg(src + c * 32);
    }
    grid_barrier();    // tokens, h0, mbar init visible grid/cluster-wide

    // phase-2 ownership (cluster-local)
    const int bl  = thr >> 5;
    const int uu  = thr & 31;
    const int b2  = ks * 8 + bl;
    const int u2  = u0 + uu;
    float hreg = 0.f, creg = 0.f;
    float biasr[4];
#pragma unroll
    for (int g = 0; g < 4; ++g) biasr[g] = bias[g * 1024 + u2];
    int tokv = g_tokens[b2 * 512];

    const uint32_t sbPart = sbB + SM_SPART;
    uint32_t rAddr[4];
#pragma unroll
    for (int r = 0; r < 4; ++r) rAddr[r] = mapa_rank(sbPart, r);
    float* zb = (float*)(sm + SM_SPART);

    // B-h staging maps (row/q fixed per thread)
    int hRowOff[8], hDst[8];
#pragma unroll
    for (int ii = 0; ii < 8; ++ii) {
        int idx  = ii * 256 + thr;
        int hsel = idx >> 10;
        int rq   = idx & 1023;
        int row  = rq >> 5, q = rq & 31;
        hRowOff[ii] = (hsel << 16) | (row * 1024 + q * 8);
        hDst[ii]    = hsel * 16896 + row * 528 + q * 16;
    }
    // x staging mapping
    const int xrow = thr >> 3;
    const int xq   = thr & 7;

    for (int t = 0; t < 512; ++t) {
        // ---- (1) issue B-h loads into regs (L2 RT hidden behind x work) ----
        const __nv_bfloat16* hcur0 = g_hh[t & 1] + ks * 256;
        const __nv_bfloat16* hcur1 = g_hl[t & 1] + ks * 256;
        uint4 hv[8];
#pragma unroll
        for (int ii = 0; ii < 8; ++ii) {
            const __nv_bfloat16* src =
                ((hRowOff[ii] >> 16) ? hcur1 : hcur0) + (hRowOff[ii] & 0xFFFF);
            hv[ii] = ldcg4((const uint4*)src);
        }
        // ---- (2) stage B-x: emb gather fp32 -> hi/lo bf16 ----
        {
            int tokx = g_tokens[xrow * 512 + t];
            const float* xs = emb + (size_t)tokx * 512 + ks * 128 + xq * 16;
            uint32_t hiw[8], low[8];
#pragma unroll
            for (int p = 0; p < 4; ++p) {
                float4 v = __ldg((const float4*)(xs + p * 4));
                float r0, r1, r2, r3;
                unsigned short h0 = bf_hi(v.x, r0), h1 = bf_hi(v.y, r1);
                unsigned short h2 = bf_hi(v.z, r2), h3 = bf_hi(v.w, r3);
                hiw[p * 2]     = (uint32_t)h0 | ((uint32_t)h1 << 16);
                hiw[p * 2 + 1] = (uint32_t)h2 | ((uint32_t)h3 << 16);
                low[p * 2]     = (uint32_t)bf_of(r0) | ((uint32_t)bf_of(r1) << 16);
                low[p * 2 + 1] = (uint32_t)bf_of(r2) | ((uint32_t)bf_of(r3) << 16);
            }
            char* xd = sm + SM_XOFF + xrow * 272 + xq * 32;
            *(uint4*)xd        = make_uint4(hiw[0], hiw[1], hiw[2], hiw[3]);
            *(uint4*)(xd + 16) = make_uint4(hiw[4], hiw[5], hiw[6], hiw[7]);
            *(uint4*)(xd + SM_XHALF)      = make_uint4(low[0], low[1], low[2], low[3]);
            *(uint4*)(xd + SM_XHALF + 16) = make_uint4(low[4], low[5], low[6], low[7]);
        }
        __syncthreads();

        float d[4][4];
#pragma unroll
        for (int nf = 0; nf < 4; ++nf)
#pragma unroll
            for (int i = 0; i < 4; ++i) d[nf][i] = 0.f;

        // ---- (3) x-chunk mma (16..23) while B-h loads are in flight ----
        {
            uint4 ahP0 = __ldg(&g_pkA_hi[abase + 16 * 32]);
            uint4 ahP1 = __ldg(&g_pkA_hi[abase + 17 * 32]);
#pragma unroll
            for (int cl = 0; cl < 8; ++cl) {
                const int c = 16 + cl;
                uint4 ah = ahP0;
                ahP0 = ahP1;
                if (cl + 2 < 8) ahP1 = __ldg(&g_pkA_hi[abase + (c + 2) * 32]);
                uint4 al = *(const uint4*)(aloPtr + c * 512);
                uint32_t a0 = sbX + nrowoff * 272 + cl * 32 + koff;
                uint32_t a1 = a0 + 16 * 272;
                uint32_t bh[8], bl8[8];
                LDSM4(bh[0], bh[1], bh[2], bh[3], a0);
                LDSM4(bh[4], bh[5], bh[6], bh[7], a1);
                LDSM4(bl8[0], bl8[1], bl8[2], bl8[3], a0 + SM_XHALF);
                LDSM4(bl8[4], bl8[5], bl8[6], bl8[7], a1 + SM_XHALF);
#pragma unroll
                for (int nf = 0; nf < 4; ++nf) {
                    MMA_BF16(d[nf], ah.x, ah.y, ah.z, ah.w, bh[nf * 2], bh[nf * 2 + 1]);
                    MMA_BF16(d[nf], ah.x, ah.y, ah.z, ah.w, bl8[nf * 2], bl8[nf * 2 + 1]);
                    MMA_BF16(d[nf], al.x, al.y, al.z, al.w, bh[nf * 2], bh[nf * 2 + 1]);
                }
            }
        }
        // ---- (4) commit B-h regs to smem, sync ----
#pragma unroll
        for (int ii = 0; ii < 8; ++ii)
            *(uint4*)(sm + hDst[ii]) = hv[ii];
        __syncthreads();

        // ---- (5) h-chunk mma (0..15) ----
        {
            uint4 ahP0 = ldcg4(&g_pkA_hi[abase]);
            uint4 ahP1 = ldcg4(&g_pkA_hi[abase + 32]);
#pragma unroll
            for (int c = 0; c < 16; ++c) {
                uint4 ah = ahP0;
                ahP0 = ahP1;
                if (c + 2 < 16) {
                    if (c + 2 < 8) ahP1 = ldcg4(&g_pkA_hi[abase + (c + 2) * 32]);
                    else           ahP1 = __ldg(&g_pkA_hi[abase + (c + 2) * 32]);
                }
                uint4 al = *(const uint4*)(aloPtr + c * 512);
                uint32_t a0 = sbB + nrowoff * 528 + c * 32 + koff;
                uint32_t a1 = a0 + 16 * 528;
                uint32_t bh[8], bl8[8];
                LDSM4(bh[0], bh[1], bh[2], bh[3], a0);
                LDSM4(bh[4], bh[5], bh[6], bh[7], a1);
                LDSM4(bl8[0], bl8[1], bl8[2], bl8[3], a0 + 16896);
                LDSM4(bl8[4], bl8[5], bl8[6], bl8[7], a1 + 16896);
#pragma unroll
                for (int nf = 0; nf < 4; ++nf) {
                    MMA_BF16(d[nf], ah.x, ah.y, ah.z, ah.w, bh[nf * 2], bh[nf * 2 + 1]);
                    MMA_BF16(d[nf], ah.x, ah.y, ah.z, ah.w, bl8[nf * 2], bl8[nf * 2 + 1]);
                    MMA_BF16(d[nf], al.x, al.y, al.z, al.w, bh[nf * 2], bh[nf * 2 + 1]);
                }
            }
        }

        // ---- partial z tile -> LOCAL smem (R14 path) ----
#pragma unroll
        for (int nf = 0; nf < 4; ++nf) {
            int bcol = nf * 8 + ((lane & 3) << 1);
            zb[bcol * 132 + m_r]        = d[nf][0];
            zb[(bcol + 1) * 132 + m_r]  = d[nf][1];
            zb[bcol * 132 + m_r8]       = d[nf][2];
            zb[(bcol + 1) * 132 + m_r8] = d[nf][3];
        }
        __syncthreads();                  // drains STS: partials are in banks
        if (thr < 4) mbar_arrive_rank(mbAddr, (uint32_t)thr);
        mbar_wait(mbAddr, t & 1);

        // ---- phase 2: pull 4 sibling partials via DSMEM, gates (R14) ----
        {
            float z[4];
#pragma unroll
            for (int g = 0; g < 4; ++g) {
                uint32_t off = (uint32_t)(b2 * 132 + g * 32 + uu) * 4;
                float s = biasr[g];
#pragma unroll
                for (int r = 0; r < 4; ++r)
                    s += ld_dsmem_f32(rAddr[r] + off);
                z[g] = s;
            }
            float gi = tanhf(z[0]);
            float gf = tanhf(z[1]);
            float gg = tanhf(z[2]);
            float go = tanhf(z[3]);
            float cn = fmaf(gf, creg, gi * gg);
            float hn = go * tanhf(cn);
            if (tokv != 0) { creg = cn; hreg = hn; }
            float rem;
            unsigned short hb = bf_hi(hreg, rem);
            int ho = b2 * 1024 + u2;
            *(unsigned short*)&g_hh[(t + 1) & 1][ho] = hb;
            *(unsigned short*)&g_hl[(t + 1) & 1][ho] = bf_of(rem);

            if (t + 1 < 512) tokv = g_tokens[b2 * 512 + t + 1];
        }
        grid_barrier();                   // h publish (flat, proven)
    }

    {
        int o = b2 * 1024 + u2;
        out[o]         = hreg;
        out[32768 + o] = hreg;
        out[65536 + o] = creg;
    }
}

// ---------------- launch ----------------
extern "C" void kernel_launch(void* const* d_in, const int* in_sizes, int n_in,
                              void* d_out, int out_size)
{
    const int*   tokens_raw = (const int*)  d_in[0];
    const float* emb        = (const float*)d_in[1];
    const float* W          = (const float*)d_in[2];
    const float* U          = (const float*)d_in[3];
    const float* bias       = (const float*)d_in[4];
    float*       out        = (float*)d_out;
    (void)in_sizes; (void)n_in; (void)out_size;

    cudaFuncSetAttribute(lstm_kernel,
                         cudaFuncAttributeMaxDynamicSharedMemorySize, SM_TOTAL);

    pack_UW_kernel<<<3072, 256>>>(U, W);
    lstm_kernel<<<NCTA, 256, SM_TOTAL>>>(tokens_raw, emb, bias, out);
}

// round 17
// speedup vs baseline: 1.1038x; 1.0584x over previous
#include <cuda_runtime.h>
#include <cuda_bf16.h>
#include <cstdint>
#include <cstddef>
#include <cstring>

// ----------------------------------------------------------------------------
// B=32, S=512, E=512, U=1024, G=4096.  out = (h, h, c) : 3*32*1024 f32
// Persistent fused kernel: z_t = [h_t ; x_t] @ [U ; W] + bias.
// Round-17 change (ONLY): A-hi chunks 0..7 cached in smem (prologue copy) ->
// zero per-step L2 traffic/latency for A operands. Base: round-14 (3496 us).
// ----------------------------------------------------------------------------
#define NCTA 128

__device__ __nv_bfloat16  g_hh[2][32768];              // h hi, [b][u]
__device__ __nv_bfloat16  g_hl[2][32768];              // h lo
__device__ uint4          g_pkA_hi[786432];            // [U;W] packed A-frags hi
__device__ uint4          g_pkA_lo[786432];            // [U;W] packed A-frags lo
__device__ int            g_tokens[16384];             // [b*512+t]
__device__ unsigned       g_cnt;
__device__ volatile unsigned g_gen;

// smem layout (dynamic, 199168 B):
//   [0      , 16896) : B-h hi   (32 rows x 528 B pitch, 512 B data)
//   [16896  , 33792) : B-h lo
//   [33792  , 42496) : B-x hi   (32 rows x 272 B pitch, 256 B data)
//   [42496  , 51200) : B-x lo
//   [51200  ,149504) : A-lo frags (8 warps x 24 chunks x 32 lanes x 16 B)
//   [149504 ,166400) : partial z tile [32 b][132 pitch] f32 (DSMEM-shared)
//   [166400 ,199168) : A-hi frags chunks 0..7 (8 warps x 8 x 32 x 16 B)
#define SM_XOFF  33792
#define SM_XHALF 8704
#define SM_ALO   51200
#define SM_SPART 149504
#define SM_AHI   166400
#define SM_TOTAL 199168

// ---------------- helpers ----------------
__device__ __forceinline__ int detect_is64(const int* raw, int thr, int* s_flag)
{
    if (thr == 0) *s_flag = 1;
    __syncthreads();
    if (thr < 128 && raw[2 * thr + 1] != 0) *s_flag = 0;
    __syncthreads();
    return *s_flag;
}
__device__ __forceinline__ unsigned short bf_hi(float f, float& rem) {
    __nv_bfloat16 b = __float2bfloat16(f);
    rem = f - __bfloat162float(b);
    unsigned short u; memcpy(&u, &b, 2); return u;
}
__device__ __forceinline__ unsigned short bf_of(float f) {
    __nv_bfloat16 b = __float2bfloat16(f);
    unsigned short u; memcpy(&u, &b, 2); return u;
}
__device__ __forceinline__ uint32_t smem_u32(const void* p) {
    uint32_t a;
    asm("{ .reg .u64 t; cvta.to.shared.u64 t, %1; cvt.u32.u64 %0, t; }" : "=r"(a) : "l"(p));
    return a;
}
__device__ __forceinline__ uint4 ldcg4(const uint4* p) {
    uint4 v;
    asm volatile("ld.global.cg.v4.u32 {%0,%1,%2,%3}, [%4];"
                 : "=r"(v.x), "=r"(v.y), "=r"(v.z), "=r"(v.w) : "l"(p));
    return v;
}
#define LDSM4(r0, r1, r2, r3, addr) \
    asm volatile("ldmatrix.sync.aligned.m8n8.x4.shared.b16 {%0,%1,%2,%3}, [%4];" \
                 : "=r"(r0), "=r"(r1), "=r"(r2), "=r"(r3) : "r"(addr))
#define MMA_BF16(d, ax, ay, az, aw, b0, b1) \
    asm volatile("mma.sync.aligned.m16n8k16.row.col.f32.bf16.bf16.f32 " \
                 "{%0,%1,%2,%3}, {%4,%5,%6,%7}, {%8,%9}, {%0,%1,%2,%3};" \
                 : "+f"((d)[0]), "+f"((d)[1]), "+f"((d)[2]), "+f"((d)[3]) \
                 : "r"(ax), "r"(ay), "r"(az), "r"(aw), "r"(b0), "r"(b1))

// mbarrier ops (cluster DSMEM sync)
__device__ __forceinline__ void mbar_init(uint32_t mb, uint32_t cnt) {
    asm volatile("mbarrier.init.shared.b64 [%0], %1;" :: "r"(mb), "r"(cnt) : "memory");
}
__device__ __forceinline__ void mbar_arrive_rank(uint32_t mb, uint32_t rank) {
    asm volatile("{\n\t.reg .b32 r;\n\t"
                 "mapa.shared::cluster.u32 r, %0, %1;\n\t"
                 "mbarrier.arrive.shared::cluster.b64 _, [r];\n\t}"
                 :: "r"(mb), "r"(rank) : "memory");
}
__device__ __forceinline__ void mbar_wait(uint32_t mb, uint32_t par) {
    asm volatile("{\n\t.reg .pred P1;\n\t"
                 "WL_%=:\n\t"
                 "mbarrier.try_wait.parity.acquire.cta.shared::cta.b64 P1, [%0], %1, 0x989680;\n\t"
                 "@P1 bra.uni WD_%=;\n\t"
                 "bra.uni WL_%=;\n\t"
                 "WD_%=:\n\t}" :: "r"(mb), "r"(par) : "memory");
}
__device__ __forceinline__ uint32_t mapa_rank(uint32_t addr, uint32_t rank) {
    uint32_t r;
    asm("mapa.shared::cluster.u32 %0, %1, %2;" : "=r"(r) : "r"(addr), "r"(rank));
    return r;
}
__device__ __forceinline__ float ld_dsmem_f32(uint32_t addr) {
    float v;
    asm volatile("ld.shared::cluster.f32 %0, [%1];" : "=f"(v) : "r"(addr));
    return v;
}

// ----------------------------------------------------------------------------
// pack [U;W] into per-thread mma A-fragment order (proven).
// ----------------------------------------------------------------------------
__global__ void __launch_bounds__(256) pack_UW_kernel(
    const float* __restrict__ U, const float* __restrict__ W)
{
    int idx  = blockIdx.x * 256 + threadIdx.x;
    int lane = idx & 31;
    int tmp  = idx >> 5;
    int c    = tmp % 24;
    int tmp2 = tmp / 24;
    int w    = tmp2 & 7;
    int cta  = tmp2 >> 3;
    int jb = cta >> 2, ks = cta & 3, u0 = jb << 5;
    int m0 = (w << 4) + (lane >> 2), m1 = m0 + 8;
    int j0 = ((m0 >> 5) << 10) + u0 + (m0 & 31);
    int j1 = ((m1 >> 5) << 10) + u0 + (m1 & 31);

    const float* base;
    if (c < 16) base = U + (size_t)((ks << 8) + (c << 4) + ((lane & 3) << 1)) * 4096;
    else        base = W + (size_t)((ks << 7) + ((c - 16) << 4) + ((lane & 3) << 1)) * 4096;

    float f[4][2];
    f[0][0] = base[j0];              f[0][1] = base[4096 + j0];
    f[1][0] = base[j1];              f[1][1] = base[4096 + j1];
    f[2][0] = base[8 * 4096 + j0];   f[2][1] = base[9 * 4096 + j0];
    f[3][0] = base[8 * 4096 + j1];   f[3][1] = base[9 * 4096 + j1];
    uint32_t hi[4], lo[4];
#pragma unroll
    for (int r = 0; r < 4; ++r) {
        float rm0, rm1;
        unsigned short h0 = bf_hi(f[r][0], rm0), h1 = bf_hi(f[r][1], rm1);
        hi[r] = (uint32_t)h0 | ((uint32_t)h1 << 16);
        lo[r] = (uint32_t)bf_of(rm0) | ((uint32_t)bf_of(rm1) << 16);
    }
    g_pkA_hi[idx] = make_uint4(hi[0], hi[1], hi[2], hi[3]);
    g_pkA_lo[idx] = make_uint4(lo[0], lo[1], lo[2], lo[3]);
}

// ---------------- grid barrier (proven) ----------------
__device__ __forceinline__ void grid_barrier()
{
    __threadfence();
    __syncthreads();
    if (threadIdx.x == 0) {
        unsigned g = g_gen;
        if (atomicAdd(&g_cnt, 1u) == (NCTA - 1u)) {
            g_cnt = 0;
            __threadfence();
            g_gen = g + 1;
        } else {
            while (g_gen == g) { __nanosleep(32); }
        }
    }
    __syncthreads();
}

// ----------------------------------------------------------------------------
// Fused LSTM scan: 32 clusters x 4 CTAs, 256 thr.  cta = jb*4 + ks, rank = ks.
// ----------------------------------------------------------------------------
__global__ void __launch_bounds__(256, 1) __cluster_dims__(4, 1, 1)
lstm_kernel(
    const int*   __restrict__ raw,
    const float* __restrict__ emb,
    const float* __restrict__ bias,
    float*       __restrict__ out)
{
    extern __shared__ __align__(16) char sm[];
    __shared__ __align__(8) unsigned long long s_mbar;
    __shared__ int s_is64;

    const int thr  = threadIdx.x;
    const int lane = thr & 31;
    const int w    = thr >> 5;
    const int cta  = blockIdx.x;
    const int ks   = cta & 3;                 // == cluster rank
    const int u0   = (cta >> 2) << 5;
    const int is64 = detect_is64(raw, thr, &s_is64);

    if (thr < 128) {
        int i = cta * 128 + thr;
        g_tokens[i] = is64 ? raw[2 * i] : raw[i];
    }
    {   // zero h buffer 0
        int zt = cta * 256 + thr;
        unsigned short z = 0;
        *(unsigned short*)&g_hh[0][zt] = z;
        *(unsigned short*)&g_hl[0][zt] = z;
    }

    const uint32_t mbAddr = smem_u32(&s_mbar);
    if (thr == 0) mbar_init(mbAddr, 4);

    // mma geometry (proven)
    const uint32_t sbB = smem_u32(sm);
    const uint32_t sbX = sbB + SM_XOFF;
    const int tile = lane >> 3, rsel = lane & 7;
    const int nrowoff = ((tile >> 1) & 1) * 8 + rsel;
    const int koff    = (tile & 1) * 16;
    const int abase   = (cta * 8 + w) * 768 + lane;    // 24 chunks * 32 lanes
    const int m_r  = (w << 4) + (lane >> 2);
    const int m_r8 = m_r + 8;

    // A-lo fragments -> private smem slots (proven win)
    char* aloPtr = sm + SM_ALO + (size_t)(w * 768 + lane) * 16;
    {
        const uint4* src = g_pkA_lo + abase;
#pragma unroll
        for (int c = 0; c < 24; ++c)
            *(uint4*)(aloPtr + c * 512) = __ldg(src + c * 32);
    }
    // NEW: A-hi chunks 0..7 -> private smem slots (kills per-step L2 stream)
    char* ahiPtr = sm + SM_AHI + (size_t)(w * 256 + lane) * 16;
    {
        const uint4* src = g_pkA_hi + abase;
#pragma unroll
        for (int c = 0; c < 8; ++c)
            *(uint4*)(ahiPtr + c * 512) = __ldg(src + c * 32);
    }
    grid_barrier();    // tokens, h0, mbar init visible grid/cluster-wide

    // phase-2 ownership (cluster-local): b = ks*8 + bl, u = u0 + uu
    const int bl  = thr >> 5;                  // 0..7
    const int uu  = thr & 31;                  // 0..31
    const int b2  = ks * 8 + bl;
    const int u2  = u0 + uu;
    float hreg = 0.f, creg = 0.f;
    float biasr[4];
#pragma unroll
    for (int g = 0; g < 4; ++g) biasr[g] = bias[g * 1024 + u2];
    int tokv = g_tokens[b2 * 512];

    // DSMEM partial-tile addresses of the 4 cluster siblings
    const uint32_t sbPart = sbB + SM_SPART;
    uint32_t rAddr[4];
#pragma unroll
    for (int r = 0; r < 4; ++r) rAddr[r] = mapa_rank(sbPart, r);
    float* zb = (float*)(sm + SM_SPART);

    // x staging mapping
    const int xrow = thr >> 3;             // 0..31  (batch row)
    const int xq   = thr & 7;              // 16 floats each

    for (int t = 0; t < 512; ++t) {
        // ---- stage B-h: h slice [32][256] hi+lo (proven layout) ----
        const __nv_bfloat16* hsrc0 = g_hh[t & 1] + ks * 256;
        const __nv_bfloat16* hsrc1 = g_hl[t & 1] + ks * 256;
#pragma unroll
        for (int ii = 0; ii < 8; ++ii) {
            int idx  = ii * 256 + thr;
            int hsel = idx >> 10;
            int rq   = idx & 1023;
            int row  = rq >> 5, q = rq & 31;
            const __nv_bfloat16* src = (hsel ? hsrc1 : hsrc0) + row * 1024;
            uint4 v = ldcg4((const uint4*)src + q);
            *(uint4*)(sm + hsel * 16896 + row * 528 + q * 16) = v;
        }
        // ---- stage B-x: emb gather [32][128] fp32 -> hi/lo bf16 ----
        {
            int tokx = g_tokens[xrow * 512 + t];
            const float* xs = emb + (size_t)tokx * 512 + ks * 128 + xq * 16;
            uint32_t hiw[8], low[8];
#pragma unroll
            for (int p = 0; p < 4; ++p) {
                float4 v = __ldg((const float4*)(xs + p * 4));
                float r0, r1, r2, r3;
                unsigned short h0 = bf_hi(v.x, r0), h1 = bf_hi(v.y, r1);
                unsigned short h2 = bf_hi(v.z, r2), h3 = bf_hi(v.w, r3);
                hiw[p * 2]     = (uint32_t)h0 | ((uint32_t)h1 << 16);
                hiw[p * 2 + 1] = (uint32_t)h2 | ((uint32_t)h3 << 16);
                low[p * 2]     = (uint32_t)bf_of(r0) | ((uint32_t)bf_of(r1) << 16);
                low[p * 2 + 1] = (uint32_t)bf_of(r2) | ((uint32_t)bf_of(r3) << 16);
            }
            char* xd = sm + SM_XOFF + xrow * 272 + xq * 32;
            *(uint4*)xd        = make_uint4(hiw[0], hiw[1], hiw[2], hiw[3]);
            *(uint4*)(xd + 16) = make_uint4(hiw[4], hiw[5], hiw[6], hiw[7]);
            *(uint4*)(xd + SM_XHALF)      = make_uint4(low[0], low[1], low[2], low[3]);
            *(uint4*)(xd + SM_XHALF + 16) = make_uint4(low[4], low[5], low[6], low[7]);
        }
        __syncthreads();

        // ---- mma mainloop: 24 k-chunks (A-hi: smem for 0..7, L1 for 8..23) ----
        float d[4][4];
#pragma unroll
        for (int nf = 0; nf < 4; ++nf)
#pragma unroll
            for (int i = 0; i < 4; ++i) d[nf][i] = 0.f;

        uint4 ahP0 = __ldg(&g_pkA_hi[abase + 8 * 32]);
        uint4 ahP1 = __ldg(&g_pkA_hi[abase + 9 * 32]);
#pragma unroll
        for (int c = 0; c < 24; ++c) {
            uint4 ah;
            if (c < 8) {
                ah = *(const uint4*)(ahiPtr + c * 512);
            } else {
                ah = ahP0;
                ahP0 = ahP1;
                if (c + 2 < 24) ahP1 = __ldg(&g_pkA_hi[abase + (c + 2) * 32]);
            }
            uint4 al = *(const uint4*)(aloPtr + c * 512);

            uint32_t a0, a1, loOff;
            if (c < 16) {
                a0 = sbB + nrowoff * 528 + c * 32 + koff;
                a1 = a0 + 16 * 528;
                loOff = 16896;
            } else {
                a0 = sbX + nrowoff * 272 + (c - 16) * 32 + koff;
                a1 = a0 + 16 * 272;
                loOff = SM_XHALF;
            }
            uint32_t bh[8], bl8[8];
            LDSM4(bh[0], bh[1], bh[2], bh[3], a0);
            LDSM4(bh[4], bh[5], bh[6], bh[7], a1);
            LDSM4(bl8[0], bl8[1], bl8[2], bl8[3], a0 + loOff);
            LDSM4(bl8[4], bl8[5], bl8[6], bl8[7], a1 + loOff);
#pragma unroll
            for (int nf = 0; nf < 4; ++nf) {
                MMA_BF16(d[nf], ah.x, ah.y, ah.z, ah.w, bh[nf * 2], bh[nf * 2 + 1]);
                MMA_BF16(d[nf], ah.x, ah.y, ah.z, ah.w, bl8[nf * 2], bl8[nf * 2 + 1]);
                MMA_BF16(d[nf], al.x, al.y, al.z, al.w, bh[nf * 2], bh[nf * 2 + 1]);
            }
        }

        // ---- partial z tile -> LOCAL smem (R14 path) ----
#pragma unroll
        for (int nf = 0; nf < 4; ++nf) {
            int bcol = nf * 8 + ((lane & 3) << 1);
            zb[bcol * 132 + m_r]        = d[nf][0];
            zb[(bcol + 1) * 132 + m_r]  = d[nf][1];
            zb[bcol * 132 + m_r8]       = d[nf][2];
            zb[(bcol + 1) * 132 + m_r8] = d[nf][3];
        }
        __syncthreads();                  // drains STS: partials are in banks
        if (thr < 4) mbar_arrive_rank(mbAddr, (uint32_t)thr);
        mbar_wait(mbAddr, t & 1);

        // ---- phase 2: pull 4 sibling partials via DSMEM, gates (R14) ----
        {
            float z[4];
#pragma unroll
            for (int g = 0; g < 4; ++g) {
                uint32_t off = (uint32_t)(b2 * 132 + g * 32 + uu) * 4;
                float s = biasr[g];
#pragma unroll
                for (int r = 0; r < 4; ++r)
                    s += ld_dsmem_f32(rAddr[r] + off);
                z[g] = s;
            }
            float gi = tanhf(z[0]);
            float gf = tanhf(z[1]);
            float gg = tanhf(z[2]);
            float go = tanhf(z[3]);
            float cn = fmaf(gf, creg, gi * gg);
            float hn = go * tanhf(cn);
            if (tokv != 0) { creg = cn; hreg = hn; }
            float rem;
            unsigned short hb = bf_hi(hreg, rem);
            int ho = b2 * 1024 + u2;
            *(unsigned short*)&g_hh[(t + 1) & 1][ho] = hb;
            *(unsigned short*)&g_hl[(t + 1) & 1][ho] = bf_of(rem);

            if (t + 1 < 512) tokv = g_tokens[b2 * 512 + t + 1];
        }
        grid_barrier();                   // h publish (the ONLY grid barrier)
    }

    {
        int o = b2 * 1024 + u2;
        out[o]         = hreg;
        out[32768 + o] = hreg;
        out[65536 + o] = creg;
    }
}

// ---------------- launch ----------------
extern "C" void kernel_launch(void* const* d_in, const int* in_sizes, int n_in,
                              void* d_out, int out_size)
{
    const int*   tokens_raw = (const int*)  d_in[0];
    const float* emb        = (const float*)d_in[1];
    const float* W          = (const float*)d_in[2];
    const float* U          = (const float*)d_in[3];
    const float* bias       = (const float*)d_in[4];
    float*       out        = (float*)d_out;
    (void)in_sizes; (void)n_in; (void)out_size;

    cudaFuncSetAttribute(lstm_kernel,
                         cudaFuncAttributeMaxDynamicSharedMemorySize, SM_TOTAL);

    pack_UW_kernel<<<3072, 256>>>(U, W);
    lstm_kernel<<<NCTA, 256, SM_TOTAL>>>(tokens_raw, emb, bias, out);
}